// round 2
// baseline (speedup 1.0000x reference)
#include <cuda_runtime.h>

// Shapes (fixed for this problem instance)
#define M_TOTAL 10752          // B*T*N = 8*64*21
#define C_IN    128
#define F_OUT   256
#define N_SP    21
#define BM      64
#define MT      (M_TOTAL / BM) // 168 M-tiles
// dynamic smem: As[64][129] + Bs[128][128] + Rsum[8][128] + Rsq[8][128]
#define SMEM_FLOATS (64*129 + 128*128 + 2*8*128)
#define SMEM_BYTES  (SMEM_FLOATS * 4)

// Scratch (device globals: allocation-free)
__device__ float g_y[M_TOTAL * F_OUT];       // 11 MB pre-BN activations
__device__ float g_psum[MT * F_OUT];         // per-(mtile,f) partial sums
__device__ float g_psq [MT * F_OUT];         // per-(mtile,f) partial sum-sq
__device__ float g_scale[F_OUT];
__device__ float g_shift[F_OUT];

typedef unsigned long long u64;

__device__ __forceinline__ u64 pkdup(float v) {
    u64 r; asm("mov.b64 %0, {%1, %1};" : "=l"(r) : "f"(v)); return r;
}
__device__ __forceinline__ u64 pk2(float lo, float hi) {
    u64 r; asm("mov.b64 %0, {%1, %2};" : "=l"(r) : "f"(lo), "f"(hi)); return r;
}
__device__ __forceinline__ void fma2(u64& d, u64 a, u64 b) {
    asm("fma.rn.f32x2 %0, %1, %2, %0;" : "+l"(d) : "l"(a), "l"(b));
}
__device__ __forceinline__ float2 up2(u64 v) {
    float2 r; asm("mov.b64 {%0, %1}, %2;" : "=f"(r.x), "=f"(r.y) : "l"(v)); return r;
}

// K1: fused spatial-shift + GEMM (fp32, f32x2 packed FMA) + per-tile BN partials
// grid (2, 168): blockIdx.x = ftile (128 cols of F), blockIdx.y = mtile (64 rows)
__global__ __launch_bounds__(128) void gemm_kernel(const float* __restrict__ x,
                                                   const float* __restrict__ W) {
    extern __shared__ float smem[];
    float* As   = smem;                 // [64][129] shifted A tile (padded rows)
    float* Bs   = smem + 64 * 129;      // [128][128] W tile
    float* Rsum = Bs + 128 * 128;       // [8][128] reduction staging
    float* Rsq  = Rsum + 8 * 128;       // [8][128]

    const int tid   = threadIdx.x;      // 0..127
    const int ftile = blockIdx.x;       // 0..1
    const int mtile = blockIdx.y;       // 0..167
    const int m0    = mtile * BM;

    // ---- load W tile (coalesced float4) ----
    {
        const float* Wf = W + ftile * 128;
        #pragma unroll
        for (int r = 0; r < 32; ++r) {
            int idx = r * 128 + tid;            // float4 index 0..4095
            int k   = idx >> 5;
            int f4  = (idx & 31) << 2;
            *(float4*)&Bs[k * 128 + f4] = *(const float4*)&Wf[k * 256 + f4];
        }
    }

    // ---- load A tile with spatial shift folded into the gather ----
    // As[i][c] = x[bt(m0+i), (n(m0+i) - c%21) mod 21, c]
    {
        const int c = tid;
        const int s = c % N_SP;
        int bt = m0 / N_SP;
        int n  = m0 - bt * N_SP;
        const float* xc = x + c;
        #pragma unroll 8
        for (int i = 0; i < BM; ++i) {
            int ns = n - s;
            ns += (ns >> 31) & N_SP;            // wrap negative
            As[i * 129 + c] = xc[(bt * N_SP + ns) << 7];
            if (++n == N_SP) { n = 0; ++bt; }
        }
    }
    __syncthreads();

    // ---- 8x8 microtile GEMM, accumulators packed as f32x2 pairs along f ----
    const int tf = tid & 15;
    const int tm = tid >> 4;
    const int f0 = tf * 8;

    u64 acc[8][4];
    #pragma unroll
    for (int i = 0; i < 8; ++i)
        #pragma unroll
        for (int j = 0; j < 4; ++j) acc[i][j] = 0ull;

    const float* Ap = As + tm * 8 * 129;
    const float* Bp = Bs + f0;

    #pragma unroll 8
    for (int k = 0; k < 128; ++k) {
        float4 b01 = *(const float4*)(Bp + k * 128);
        float4 b23 = *(const float4*)(Bp + k * 128 + 4);
        u64 bv0 = pk2(b01.x, b01.y);
        u64 bv1 = pk2(b01.z, b01.w);
        u64 bv2 = pk2(b23.x, b23.y);
        u64 bv3 = pk2(b23.z, b23.w);
        #pragma unroll
        for (int i = 0; i < 8; ++i) {
            u64 av = pkdup(Ap[i * 129 + k]);
            fma2(acc[i][0], av, bv0);
            fma2(acc[i][1], av, bv1);
            fma2(acc[i][2], av, bv2);
            fma2(acc[i][3], av, bv3);
        }
    }

    // ---- epilogue: write y, accumulate per-thread BN partials ----
    // (conv bias b cancels exactly in BN, so it is omitted)
    float psum[8], psq[8];
    #pragma unroll
    for (int l = 0; l < 8; ++l) { psum[l] = 0.f; psq[l] = 0.f; }

    const int fg = ftile * 128 + f0;
    #pragma unroll
    for (int i = 0; i < 8; ++i) {
        float2 v0 = up2(acc[i][0]);
        float2 v1 = up2(acc[i][1]);
        float2 v2 = up2(acc[i][2]);
        float2 v3 = up2(acc[i][3]);
        float* yr = g_y + (size_t)(m0 + tm * 8 + i) * F_OUT + fg;
        *(float4*)(yr)     = make_float4(v0.x, v0.y, v1.x, v1.y);
        *(float4*)(yr + 4) = make_float4(v2.x, v2.y, v3.x, v3.y);
        psum[0] += v0.x; psq[0] += v0.x * v0.x;
        psum[1] += v0.y; psq[1] += v0.y * v0.y;
        psum[2] += v1.x; psq[2] += v1.x * v1.x;
        psum[3] += v1.y; psq[3] += v1.y * v1.y;
        psum[4] += v2.x; psq[4] += v2.x * v2.x;
        psum[5] += v2.y; psq[5] += v2.y * v2.y;
        psum[6] += v3.x; psq[6] += v3.x * v3.x;
        psum[7] += v3.y; psq[7] += v3.y * v3.y;
    }

    #pragma unroll
    for (int l = 0; l < 8; ++l) {
        Rsum[tm * 128 + f0 + l] = psum[l];
        Rsq [tm * 128 + f0 + l] = psq[l];
    }
    __syncthreads();

    // deterministic tree over the 8 tm groups, one f per thread
    {
        const int f = tid;
        float s = 0.f, q = 0.f;
        #pragma unroll
        for (int r = 0; r < 8; ++r) {
            s += Rsum[r * 128 + f];
            q += Rsq [r * 128 + f];
        }
        g_psum[mtile * F_OUT + ftile * 128 + f] = s;
        g_psq [mtile * F_OUT + ftile * 128 + f] = q;
    }
}

// K2: finalize BN statistics -> per-f scale/shift
__global__ void stats_kernel(const float* __restrict__ gamma,
                             const float* __restrict__ beta) {
    const int f = threadIdx.x;  // 256 threads
    float s = 0.f, q = 0.f;
    for (int t = 0; t < MT; ++t) {
        s += g_psum[t * F_OUT + f];
        q += g_psq [t * F_OUT + f];
    }
    const float inv = 1.0f / (float)M_TOTAL;
    float mean = s * inv;
    float var  = q * inv - mean * mean;
    float sc   = gamma[f] * rsqrtf(var + 1e-3f);
    g_scale[f] = sc;
    g_shift[f] = beta[f] - mean * sc;
}

// K3: normalize + relu (vectorized float4)
__global__ __launch_bounds__(256) void norm_kernel(float* __restrict__ out) {
    const int idx = blockIdx.x * 256 + threadIdx.x;    // float4 index
    float4 y = *(const float4*)&g_y[(size_t)idx * 4];
    const int fb = (idx & 63) * 4;                     // F_OUT/4 = 64 groups
    float4 sc = *(const float4*)&g_scale[fb];
    float4 sh = *(const float4*)&g_shift[fb];
    float4 o;
    o.x = fmaxf(fmaf(y.x, sc.x, sh.x), 0.f);
    o.y = fmaxf(fmaf(y.y, sc.y, sh.y), 0.f);
    o.z = fmaxf(fmaf(y.z, sc.z, sh.z), 0.f);
    o.w = fmaxf(fmaf(y.w, sc.w, sh.w), 0.f);
    *(float4*)&out[(size_t)idx * 4] = o;
}

extern "C" void kernel_launch(void* const* d_in, const int* in_sizes, int n_in,
                              void* d_out, int out_size) {
    const float* x     = (const float*)d_in[0];
    const float* W     = (const float*)d_in[1];
    // d_in[2] = conv bias b: cancels exactly under BatchNorm -> unused
    const float* gamma = (const float*)d_in[3];
    const float* beta  = (const float*)d_in[4];

    cudaFuncSetAttribute(gemm_kernel, cudaFuncAttributeMaxDynamicSharedMemorySize,
                         SMEM_BYTES);

    gemm_kernel<<<dim3(2, MT), 128, SMEM_BYTES>>>(x, W);
    stats_kernel<<<1, 256>>>(gamma, beta);
    norm_kernel<<<(M_TOTAL * F_OUT) / (256 * 4), 256>>>((float*)d_out);
}

// round 3
// speedup vs baseline: 1.1178x; 1.1178x over previous
#include <cuda_runtime.h>

// Shapes (fixed for this problem instance)
#define M_TOTAL 10752          // B*T*N = 8*64*21
#define C_IN    128
#define F_OUT   256
#define N_SP    21
#define BM      64
#define MT      (M_TOTAL / BM) // 168 M-tiles
#define AS_STRIDE 68           // [k][m] tile row stride (16B aligned, 4-way max bank)
// dynamic smem: As[128][68] + Bs[128][128] + Rsum[8][128] + Rsq[8][128]
#define SMEM_FLOATS (128*AS_STRIDE + 128*128 + 2*8*128)
#define SMEM_BYTES  (SMEM_FLOATS * 4)

// Scratch (device globals: allocation-free)
__device__ float g_y[M_TOTAL * F_OUT];       // 11 MB pre-BN activations
__device__ float g_psum[MT * F_OUT];         // per-(mtile,f) partial sums
__device__ float g_psq [MT * F_OUT];         // per-(mtile,f) partial sum-sq
__device__ float g_scale[F_OUT];
__device__ float g_shift[F_OUT];

typedef unsigned long long u64;

__device__ __forceinline__ u64 pkdup(float v) {
    u64 r; asm("mov.b64 %0, {%1, %1};" : "=l"(r) : "f"(v)); return r;
}
__device__ __forceinline__ void fma2(u64& d, u64 a, u64 b) {
    asm("fma.rn.f32x2 %0, %1, %2, %0;" : "+l"(d) : "l"(a), "l"(b));
}
__device__ __forceinline__ void add2(u64& d, u64 a) {
    asm("add.rn.f32x2 %0, %0, %1;" : "+l"(d) : "l"(a));
}
__device__ __forceinline__ float2 up2(u64 v) {
    float2 r; asm("mov.b64 {%0, %1}, %2;" : "=f"(r.x), "=f"(r.y) : "l"(v)); return r;
}

// K1: fused spatial-shift + GEMM (fp32, f32x2 packed FMA) + per-tile BN partials
// grid (2, 168): blockIdx.x = ftile (128 cols of F), blockIdx.y = mtile (64 rows)
// Accumulators are packed along M; A tile stored transposed [k][m] so the
// 128-bit shared loads deliver ready-packed m-pairs (no pack MOVs for A).
__global__ __launch_bounds__(128, 2) void gemm_kernel(const float* __restrict__ x,
                                                      const float* __restrict__ W) {
    extern __shared__ float smem[];
    float* As   = smem;                        // [128][AS_STRIDE]  (k-major)
    float* Bs   = smem + 128 * AS_STRIDE;      // [128][128]
    float* Rsum = Bs + 128 * 128;              // [8][128]
    float* Rsq  = Rsum + 8 * 128;              // [8][128]

    const int tid   = threadIdx.x;      // 0..127
    const int ftile = blockIdx.x;       // 0..1
    const int mtile = blockIdx.y;       // 0..167
    const int m0    = mtile * BM;

    // ---- load W tile (coalesced float4) ----
    {
        const float* Wf = W + ftile * 128;
        #pragma unroll
        for (int r = 0; r < 32; ++r) {
            int idx = r * 128 + tid;            // float4 index 0..4095
            int k   = idx >> 5;
            int f4  = (idx & 31) << 2;
            *(float4*)&Bs[k * 128 + f4] = *(const float4*)&Wf[k * 256 + f4];
        }
    }

    // ---- load A tile (transposed, shift folded into gather) ----
    // As[c][i] = x[bt(m0+i), (n(m0+i) - c%21) mod 21, c]
    {
        const int c = tid;                       // channel == k
        const int s = c % N_SP;
        int bt = m0 / N_SP;
        int n  = m0 - bt * N_SP;
        const float* xc = x + c;
        float* Ac = As + c * AS_STRIDE;
        #pragma unroll 8
        for (int i = 0; i < BM; ++i) {
            int ns = n - s;
            ns += (ns >> 31) & N_SP;            // wrap negative
            Ac[i] = xc[(bt * N_SP + ns) << 7];
            if (++n == N_SP) { n = 0; ++bt; }
        }
    }
    __syncthreads();

    // ---- 8x8 microtile GEMM: acc[f][m-pair], all packed f32x2 ----
    const int tf = tid & 15;            // 16 f-groups of 8
    const int tm = tid >> 4;            // 8 m-groups of 8
    const int f0 = tf * 8;

    u64 acc[8][4];
    #pragma unroll
    for (int j = 0; j < 8; ++j)
        #pragma unroll
        for (int p = 0; p < 4; ++p) acc[j][p] = 0ull;

    const float* Ap = As + tm * 8;      // + k*AS_STRIDE
    const float* Bp = Bs + f0;          // + k*128

    #pragma unroll 4
    for (int k = 0; k < 128; ++k) {
        // A fragment: 8 rows = 4 packed m-pairs, straight from LDS.128
        ulonglong2 a01 = *(const ulonglong2*)(Ap + k * AS_STRIDE);
        ulonglong2 a23 = *(const ulonglong2*)(Ap + k * AS_STRIDE + 4);
        // B fragment: 8 scalars (2 LDS.128), dup'd per f
        float4 b03 = *(const float4*)(Bp + k * 128);
        float4 b47 = *(const float4*)(Bp + k * 128 + 4);
        const float bf[8] = { b03.x, b03.y, b03.z, b03.w,
                              b47.x, b47.y, b47.z, b47.w };
        #pragma unroll
        for (int j = 0; j < 8; ++j) {
            u64 bd = pkdup(bf[j]);
            fma2(acc[j][0], a01.x, bd);
            fma2(acc[j][1], a01.y, bd);
            fma2(acc[j][2], a23.x, bd);
            fma2(acc[j][3], a23.y, bd);
        }
    }

    // ---- epilogue: write y, accumulate packed BN partials ----
    // (conv bias b cancels exactly in BN, so it is omitted)
    u64 psum2[8], psq2[8];
    #pragma unroll
    for (int j = 0; j < 8; ++j) { psum2[j] = 0ull; psq2[j] = 0ull; }

    const int fg = ftile * 128 + f0;
    #pragma unroll
    for (int p = 0; p < 4; ++p) {
        float2 v[8];
        #pragma unroll
        for (int j = 0; j < 8; ++j) {
            v[j] = up2(acc[j][p]);
            add2(psum2[j], acc[j][p]);
            fma2(psq2[j],  acc[j][p], acc[j][p]);
        }
        float* ylo = g_y + (size_t)(m0 + tm * 8 + 2 * p) * F_OUT + fg;
        float* yhi = ylo + F_OUT;
        *(float4*)(ylo)     = make_float4(v[0].x, v[1].x, v[2].x, v[3].x);
        *(float4*)(ylo + 4) = make_float4(v[4].x, v[5].x, v[6].x, v[7].x);
        *(float4*)(yhi)     = make_float4(v[0].y, v[1].y, v[2].y, v[3].y);
        *(float4*)(yhi + 4) = make_float4(v[4].y, v[5].y, v[6].y, v[7].y);
    }

    #pragma unroll
    for (int j = 0; j < 8; ++j) {
        float2 s = up2(psum2[j]);
        float2 q = up2(psq2[j]);
        Rsum[tm * 128 + f0 + j] = s.x + s.y;
        Rsq [tm * 128 + f0 + j] = q.x + q.y;
    }
    __syncthreads();

    // deterministic tree over the 8 tm groups, one f per thread
    {
        const int f = tid;
        float s = 0.f, q = 0.f;
        #pragma unroll
        for (int r = 0; r < 8; ++r) {
            s += Rsum[r * 128 + f];
            q += Rsq [r * 128 + f];
        }
        g_psum[mtile * F_OUT + ftile * 128 + f] = s;
        g_psq [mtile * F_OUT + ftile * 128 + f] = q;
    }
}

// K2: finalize BN statistics -> per-f scale/shift (1024 threads, 4-way split)
__global__ __launch_bounds__(1024) void stats_kernel(const float* __restrict__ gamma,
                                                     const float* __restrict__ beta) {
    __shared__ float ss[4][256], sq[4][256];
    const int tid = threadIdx.x;
    const int f = tid & 255;
    const int g = tid >> 8;             // 0..3, each sums 42 tiles
    float s = 0.f, q = 0.f;
    #pragma unroll 6
    for (int t = g * 42; t < (g + 1) * 42; ++t) {
        s += g_psum[t * F_OUT + f];
        q += g_psq [t * F_OUT + f];
    }
    ss[g][f] = s; sq[g][f] = q;
    __syncthreads();
    if (g == 0) {
        s = ss[0][f] + ss[1][f] + ss[2][f] + ss[3][f];
        q = sq[0][f] + sq[1][f] + sq[2][f] + sq[3][f];
        const float inv = 1.0f / (float)M_TOTAL;
        float mean = s * inv;
        float var  = q * inv - mean * mean;
        float sc   = gamma[f] * rsqrtf(var + 1e-3f);
        g_scale[f] = sc;
        g_shift[f] = beta[f] - mean * sc;
    }
}

// K3: normalize + relu (vectorized float4)
__global__ __launch_bounds__(256) void norm_kernel(float* __restrict__ out) {
    const int idx = blockIdx.x * 256 + threadIdx.x;    // float4 index
    float4 y = *(const float4*)&g_y[(size_t)idx * 4];
    const int fb = (idx & 63) * 4;                     // F_OUT/4 = 64 groups
    float4 sc = *(const float4*)&g_scale[fb];
    float4 sh = *(const float4*)&g_shift[fb];
    float4 o;
    o.x = fmaxf(fmaf(y.x, sc.x, sh.x), 0.f);
    o.y = fmaxf(fmaf(y.y, sc.y, sh.y), 0.f);
    o.z = fmaxf(fmaf(y.z, sc.z, sh.z), 0.f);
    o.w = fmaxf(fmaf(y.w, sc.w, sh.w), 0.f);
    *(float4*)&out[(size_t)idx * 4] = o;
}

extern "C" void kernel_launch(void* const* d_in, const int* in_sizes, int n_in,
                              void* d_out, int out_size) {
    const float* x     = (const float*)d_in[0];
    const float* W     = (const float*)d_in[1];
    // d_in[2] = conv bias b: cancels exactly under BatchNorm -> unused
    const float* gamma = (const float*)d_in[3];
    const float* beta  = (const float*)d_in[4];

    cudaFuncSetAttribute(gemm_kernel, cudaFuncAttributeMaxDynamicSharedMemorySize,
                         SMEM_BYTES);

    gemm_kernel<<<dim3(2, MT), 128, SMEM_BYTES>>>(x, W);
    stats_kernel<<<1, 1024>>>(gamma, beta);
    norm_kernel<<<(M_TOTAL * F_OUT) / (256 * 4), 256>>>((float*)d_out);
}

// round 5
// speedup vs baseline: 1.2295x; 1.0999x over previous
#include <cuda_runtime.h>

// Shapes (fixed for this problem instance)
#define M_TOTAL 10752          // B*T*N = 8*64*21
#define C_IN    128
#define F_OUT   256
#define N_SP    21
#define BM      64
#define MT      (M_TOTAL / BM) // 168 M-tiles
#define AS_STRIDE 68           // [k][m] tile row stride (16B aligned, 4-way max bank)
// dynamic smem: As[128][68] + Bs[128][128] + Rsum[8][128] + Rsq[8][128]
#define SMEM_FLOATS (128*AS_STRIDE + 128*128 + 2*8*128)
#define SMEM_BYTES  (SMEM_FLOATS * 4)

// Scratch (device globals: allocation-free)
__device__ float g_y[M_TOTAL * F_OUT];       // 11 MB pre-BN activations
__device__ float g_psum[MT * F_OUT];         // per-(mtile,f) partial sums
__device__ float g_psq [MT * F_OUT];         // per-(mtile,f) partial sum-sq
__device__ float g_scale[F_OUT];
__device__ float g_shift[F_OUT];

typedef unsigned long long u64;

__device__ __forceinline__ u64 pkdup(float v) {
    u64 r; asm("mov.b64 %0, {%1, %1};" : "=l"(r) : "f"(v)); return r;
}
__device__ __forceinline__ void fma2(u64& d, u64 a, u64 b) {
    asm("fma.rn.f32x2 %0, %1, %2, %0;" : "+l"(d) : "l"(a), "l"(b));
}
__device__ __forceinline__ void add2(u64& d, u64 a) {
    asm("add.rn.f32x2 %0, %0, %1;" : "+l"(d) : "l"(a));
}
__device__ __forceinline__ float2 up2(u64 v) {
    float2 r; asm("mov.b64 {%0, %1}, %2;" : "=f"(r.x), "=f"(r.y) : "l"(v)); return r;
}

// K1: fused spatial-shift + GEMM (fp32, f32x2 packed FMA) + per-tile BN partials
// grid (2, 168), 256 threads. Microtile per thread: 8 m (4 packed f32x2 pairs)
// x 4 f. Within a warp tm is constant -> A-fragment LDS are pure broadcasts.
// 16 warps/SM (2 CTAs) for latency hiding; issue floor unchanged vs 128-thr.
__global__ __launch_bounds__(256, 2) void gemm_kernel(const float* __restrict__ x,
                                                      const float* __restrict__ W) {
    extern __shared__ float smem[];
    float* As   = smem;                        // [128][AS_STRIDE]  (k-major)
    float* Bs   = smem + 128 * AS_STRIDE;      // [128][128]
    float* Rsum = Bs + 128 * 128;              // [8][128]
    float* Rsq  = Rsum + 8 * 128;              // [8][128]

    const int tid   = threadIdx.x;      // 0..255
    const int ftile = blockIdx.x;       // 0..1
    const int mtile = blockIdx.y;       // 0..167
    const int m0    = mtile * BM;

    // ---- load W tile (coalesced float4) ----
    {
        const float* Wf = W + ftile * 128;
        #pragma unroll
        for (int r = 0; r < 16; ++r) {
            int idx = r * 256 + tid;            // float4 index 0..4095
            int k   = idx >> 5;
            int f4  = (idx & 31) << 2;
            *(float4*)&Bs[k * 128 + f4] = *(const float4*)&Wf[k * 256 + f4];
        }
    }

    // ---- load A tile (transposed, shift folded into gather) ----
    // As[c][i] = x[bt(m0+i), (n(m0+i) - c%21) mod 21, c]
    {
        const int c    = tid & 127;              // channel == k
        const int half = tid >> 7;               // 0..1: 32 rows each
        const int s = c % N_SP;
        const int i0 = half * 32;
        int bt = (m0 + i0) / N_SP;
        int n  = (m0 + i0) - bt * N_SP;
        const float* xc = x + c;
        float* Ac = As + c * AS_STRIDE + i0;
        #pragma unroll 8
        for (int i = 0; i < 32; ++i) {
            int ns = n - s;
            ns += (ns >> 31) & N_SP;            // wrap negative
            Ac[i] = xc[(bt * N_SP + ns) << 7];
            if (++n == N_SP) { n = 0; ++bt; }
        }
    }
    __syncthreads();

    // ---- microtile GEMM: acc[f][m-pair], packed f32x2 along m ----
    const int tf = tid & 31;            // 32 f-groups of 4
    const int tm = tid >> 5;            // 8 m-groups of 8 (constant per warp)
    const int f0 = tf * 4;

    u64 acc[4][4];
    #pragma unroll
    for (int j = 0; j < 4; ++j)
        #pragma unroll
        for (int p = 0; p < 4; ++p) acc[j][p] = 0ull;

    const float* Ap = As + tm * 8;      // + k*AS_STRIDE (broadcast within warp)
    const float* Bp = Bs + f0;          // + k*128

    #pragma unroll 8
    for (int k = 0; k < 128; ++k) {
        // A fragment: 8 rows = 4 packed m-pairs (2x LDS.128, broadcast)
        ulonglong2 a01 = *(const ulonglong2*)(Ap + k * AS_STRIDE);
        ulonglong2 a23 = *(const ulonglong2*)(Ap + k * AS_STRIDE + 4);
        // B fragment: 4 scalars (1x LDS.128), dup'd per f
        float4 b = *(const float4*)(Bp + k * 128);
        const float bf[4] = { b.x, b.y, b.z, b.w };
        #pragma unroll
        for (int j = 0; j < 4; ++j) {
            u64 bd = pkdup(bf[j]);
            fma2(acc[j][0], a01.x, bd);
            fma2(acc[j][1], a01.y, bd);
            fma2(acc[j][2], a23.x, bd);
            fma2(acc[j][3], a23.y, bd);
        }
    }

    // ---- epilogue: write y, accumulate packed BN partials ----
    // (conv bias b cancels exactly in BN, so it is omitted)
    u64 psum2[4], psq2[4];
    #pragma unroll
    for (int j = 0; j < 4; ++j) { psum2[j] = 0ull; psq2[j] = 0ull; }

    const int fg = ftile * 128 + f0;
    #pragma unroll
    for (int p = 0; p < 4; ++p) {
        float2 v[4];
        #pragma unroll
        for (int j = 0; j < 4; ++j) {
            v[j] = up2(acc[j][p]);
            add2(psum2[j], acc[j][p]);
            fma2(psq2[j],  acc[j][p], acc[j][p]);
        }
        float* ylo = g_y + (size_t)(m0 + tm * 8 + 2 * p) * F_OUT + fg;
        *(float4*)(ylo)         = make_float4(v[0].x, v[1].x, v[2].x, v[3].x);
        *(float4*)(ylo + F_OUT) = make_float4(v[0].y, v[1].y, v[2].y, v[3].y);
    }

    #pragma unroll
    for (int j = 0; j < 4; ++j) {
        float2 s = up2(psum2[j]);
        float2 q = up2(psq2[j]);
        Rsum[tm * 128 + f0 + j] = s.x + s.y;
        Rsq [tm * 128 + f0 + j] = q.x + q.y;
    }
    __syncthreads();

    // deterministic tree over the 8 tm groups, one f per thread (threads 0..127)
    if (tid < 128) {
        const int f = tid;
        float s = 0.f, q = 0.f;
        #pragma unroll
        for (int r = 0; r < 8; ++r) {
            s += Rsum[r * 128 + f];
            q += Rsq [r * 128 + f];
        }
        g_psum[mtile * F_OUT + ftile * 128 + f] = s;
        g_psq [mtile * F_OUT + ftile * 128 + f] = q;
    }
}

// K2: finalize BN statistics -> per-f scale/shift (1024 threads, 4-way split)
__global__ __launch_bounds__(1024) void stats_kernel(const float* __restrict__ gamma,
                                                     const float* __restrict__ beta) {
    __shared__ float ss[4][256], sq[4][256];
    const int tid = threadIdx.x;
    const int f = tid & 255;
    const int g = tid >> 8;             // 0..3, each sums 42 tiles
    float s = 0.f, q = 0.f;
    #pragma unroll 6
    for (int t = g * 42; t < (g + 1) * 42; ++t) {
        s += g_psum[t * F_OUT + f];
        q += g_psq [t * F_OUT + f];
    }
    ss[g][f] = s; sq[g][f] = q;
    __syncthreads();
    if (g == 0) {
        s = ss[0][f] + ss[1][f] + ss[2][f] + ss[3][f];
        q = sq[0][f] + sq[1][f] + sq[2][f] + sq[3][f];
        const float inv = 1.0f / (float)M_TOTAL;
        float mean = s * inv;
        float var  = q * inv - mean * mean;
        float sc   = gamma[f] * rsqrtf(var + 1e-3f);
        g_scale[f] = sc;
        g_shift[f] = beta[f] - mean * sc;
    }
}

// K3: normalize + relu (vectorized float4)
__global__ __launch_bounds__(512) void norm_kernel(float* __restrict__ out) {
    const int idx = blockIdx.x * 512 + threadIdx.x;    // float4 index
    float4 y = *(const float4*)&g_y[(size_t)idx * 4];
    const int fb = (idx & 63) * 4;                     // F_OUT/4 = 64 groups
    float4 sc = *(const float4*)&g_scale[fb];
    float4 sh = *(const float4*)&g_shift[fb];
    float4 o;
    o.x = fmaxf(fmaf(y.x, sc.x, sh.x), 0.f);
    o.y = fmaxf(fmaf(y.y, sc.y, sh.y), 0.f);
    o.z = fmaxf(fmaf(y.z, sc.z, sh.z), 0.f);
    o.w = fmaxf(fmaf(y.w, sc.w, sh.w), 0.f);
    *(float4*)&out[(size_t)idx * 4] = o;
}

extern "C" void kernel_launch(void* const* d_in, const int* in_sizes, int n_in,
                              void* d_out, int out_size) {
    const float* x     = (const float*)d_in[0];
    const float* W     = (const float*)d_in[1];
    // d_in[2] = conv bias b: cancels exactly under BatchNorm -> unused
    const float* gamma = (const float*)d_in[3];
    const float* beta  = (const float*)d_in[4];

    cudaFuncSetAttribute(gemm_kernel, cudaFuncAttributeMaxDynamicSharedMemorySize,
                         SMEM_BYTES);

    gemm_kernel<<<dim3(2, MT), 256, SMEM_BYTES>>>(x, W);
    stats_kernel<<<1, 1024>>>(gamma, beta);
    norm_kernel<<<(M_TOTAL * F_OUT) / (512 * 4), 512>>>((float*)d_out);
}